// round 1
// baseline (speedup 1.0000x reference)
#include <cuda_runtime.h>
#include <cstdint>

// ---------------------------------------------------------------------------
// RelationalKENN: unary clause enhancement + binary (edge) clause enhancement
//   up = (unary + d_unary) scatter-added with edge deltas at index1/index2
//   bp = binary + d_binary
// Output layout: [ up : n_nodes*16 floats ][ bp : n_edges*4 floats ]
// ---------------------------------------------------------------------------

#define MAX_NODES 100096  // problem fixes n_nodes = 100000

// Pre-scatter u columns 0..3 per node (only cols 0..3 feed the binary clauses).
// Must be separate from d_out because kernel B atomically mutates d_out's up
// region while also needing the original u values.
__device__ float4 g_u03[MAX_NODES];

__global__ void __launch_bounds__(256)
unary_enhance_kernel(const float* __restrict__ unary,
                     const float* __restrict__ w,
                     float*       __restrict__ up,       // d_out up region
                     int n_nodes)
{
    int row = blockIdx.x * blockDim.x + threadIdx.x;
    if (row >= n_nodes) return;

    const float4* in4 = reinterpret_cast<const float4*>(unary) + (size_t)row * 4;
    float4 a = in4[0], b = in4[1], c = in4[2], d = in4[3];
    float x[16] = { a.x, a.y, a.z, a.w,  b.x, b.y, b.z, b.w,
                    c.x, c.y, c.z, c.w,  d.x, d.y, d.z, d.w };
    float dlt[16];
#pragma unroll
    for (int i = 0; i < 16; i++) dlt[i] = 0.0f;

    // clause with 2 literals, signs (-1, +1)
    auto clause2 = [&](int i, int j, float wt) {
        float ea = __expf(-x[i]);
        float eb = __expf( x[j]);
        float r  = __fdividef(wt, ea + eb);
        dlt[i] -= ea * r;
        dlt[j] += eb * r;
    };
    // clause with 3 literals, signs (-1, +1, +1)
    auto clause3 = [&](int i, int j, int k, float wt) {
        float ea = __expf(-x[i]);
        float eb = __expf( x[j]);
        float ec = __expf( x[k]);
        float r  = __fdividef(wt, ea + eb + ec);
        dlt[i] -= ea * r;
        dlt[j] += eb * r;
        dlt[k] += ec * r;
    };

    clause2(0, 1,      w[0]);
    clause2(1, 2,      w[1]);
    clause3(2, 3, 4,   w[2]);
    clause2(4, 5,      w[3]);
    clause3(6, 7, 8,   w[4]);
    clause2(8, 9,      w[5]);
    clause3(10, 11, 12, w[6]);
    clause3(13, 14, 15, w[7]);

    float u[16];
#pragma unroll
    for (int i = 0; i < 16; i++) u[i] = x[i] + dlt[i];

    float4* o4 = reinterpret_cast<float4*>(up) + (size_t)row * 4;
    o4[0] = make_float4(u[0],  u[1],  u[2],  u[3]);
    o4[1] = make_float4(u[4],  u[5],  u[6],  u[7]);
    o4[2] = make_float4(u[8],  u[9],  u[10], u[11]);
    o4[3] = make_float4(u[12], u[13], u[14], u[15]);

    g_u03[row] = make_float4(u[0], u[1], u[2], u[3]);
}

__global__ void __launch_bounds__(256)
binary_enhance_kernel(const float* __restrict__ binary,
                      const int*   __restrict__ index1,
                      const int*   __restrict__ index2,
                      const float* __restrict__ w,
                      float*       __restrict__ up,      // atomic target
                      float*       __restrict__ bp,      // d_out bp region
                      int n_edges)
{
    int e = blockIdx.x * blockDim.x + threadIdx.x;
    if (e >= n_edges) return;

    int i1 = index1[e];
    int i2 = index2[e];
    float4 v1 = g_u03[i1];
    float4 v2 = g_u03[i2];
    float4 bv = reinterpret_cast<const float4*>(binary)[e];

    float U1[4] = { v1.x, v1.y, v1.z, v1.w };
    float U2[4] = { v2.x, v2.y, v2.z, v2.w };
    float B [4] = { bv.x, bv.y, bv.z, bv.w };
    float W [4] = { w[0], w[1], w[2], w[3] };

    float du1[4], du2[4], bo[4];
#pragma unroll
    for (int k = 0; k < 4; k++) {
        // clause k: literals (u1[k]:-1, binary[k]:-1, u2[k]:+1)
        float ea = __expf(-U1[k]);
        float eb = __expf(-B[k]);
        float ec = __expf( U2[k]);
        float r  = __fdividef(W[k], ea + eb + ec);
        du1[k] = -ea * r;
        bo[k]  =  B[k] - eb * r;   // bp = binary + db
        du2[k] =  ec * r;
    }

    reinterpret_cast<float4*>(bp)[e] = make_float4(bo[0], bo[1], bo[2], bo[3]);

    // Vectorized no-return reductions: one 16B red per node-side instead of
    // 4 scalar atomicAdds. Node rows are 64B apart -> 16B aligned targets.
    float* p1 = up + (size_t)i1 * 16;
    float* p2 = up + (size_t)i2 * 16;
    asm volatile("red.global.add.v4.f32 [%0], {%1, %2, %3, %4};"
                 :: "l"(p1), "f"(du1[0]), "f"(du1[1]), "f"(du1[2]), "f"(du1[3])
                 : "memory");
    asm volatile("red.global.add.v4.f32 [%0], {%1, %2, %3, %4};"
                 :: "l"(p2), "f"(du2[0]), "f"(du2[1]), "f"(du2[2]), "f"(du2[3])
                 : "memory");
}

extern "C" void kernel_launch(void* const* d_in, const int* in_sizes, int n_in,
                              void* d_out, int out_size)
{
    const float* unary   = (const float*)d_in[0];
    const float* binary  = (const float*)d_in[1];
    const int*   index1  = (const int*)  d_in[2];
    const int*   index2  = (const int*)  d_in[3];
    const float* uw      = (const float*)d_in[4];
    const float* bw      = (const float*)d_in[5];

    int n_nodes = in_sizes[0] / 16;
    int n_edges = in_sizes[2];

    float* up = (float*)d_out;
    float* bp = up + (size_t)n_nodes * 16;

    unary_enhance_kernel<<<(n_nodes + 255) / 256, 256>>>(unary, uw, up, n_nodes);
    binary_enhance_kernel<<<(n_edges + 255) / 256, 256>>>(binary, index1, index2,
                                                          bw, up, bp, n_edges);
}